// round 3
// baseline (speedup 1.0000x reference)
#include <cuda_runtime.h>
#include <math.h>

// ---------------- problem constants ----------------
#define NBATCH 1024
#define TSRC   32
#define TOUT   64
#define WARM   24
#define NT1    96      // rec threads: 4 j-groups (6 joints) x 24 k
#define NT2    192     // dec threads

typedef unsigned long long ull;

// staging buffer for decode outputs o: [N, T, J*H]
__device__ float g_O[(size_t)NBATCH * TOUT * 576];

// SMPL tree adjacency incl. self-loop
__constant__ int c_nbr[24][5] = {
    {0,1,2,3,-1},{1,0,4,-1,-1},{2,0,5,-1,-1},{3,0,6,-1,-1},
    {4,1,7,-1,-1},{5,2,8,-1,-1},{6,3,9,-1,-1},{7,4,10,-1,-1},
    {8,5,11,-1,-1},{9,6,12,13,14},{10,7,-1,-1,-1},{11,8,-1,-1,-1},
    {12,9,15,-1,-1},{13,9,16,-1,-1},{14,9,17,-1,-1},{15,12,-1,-1,-1},
    {16,13,18,-1,-1},{17,14,19,-1,-1},{18,16,20,-1,-1},{19,17,21,-1,-1},
    {20,18,22,-1,-1},{21,19,23,-1,-1},{22,20,-1,-1,-1},{23,21,-1,-1,-1}};
__constant__ int c_cnt[24] = {4,3,3,3, 3,3,3,3, 3,5,2,2, 3,3,3,2, 3,3,3,3, 3,3,2,2};
__constant__ float c_inv[24] = {
    1.f/4,1.f/3,1.f/3,1.f/3, 1.f/3,1.f/3,1.f/3,1.f/3,
    1.f/3,1.f/5,1.f/2,1.f/2, 1.f/3,1.f/3,1.f/3,1.f/2,
    1.f/3,1.f/3,1.f/3,1.f/3, 1.f/3,1.f/3,1.f/2,1.f/2};

// ---- Blackwell packed fp32 helpers ----
__device__ __forceinline__ ull splat2(float x) {
    ull d; asm("mov.b64 %0, {%1, %1};" : "=l"(d) : "f"(x)); return d;
}
__device__ __forceinline__ ull fma2(ull a, ull b, ull c) {
    ull d; asm("fma.rn.f32x2 %0, %1, %2, %3;" : "=l"(d) : "l"(a), "l"(b), "l"(c));
    return d;
}
__device__ __forceinline__ void unpack2(ull a, float& lo, float& hi) {
    asm("mov.b64 {%0, %1}, %2;" : "=f"(lo), "=f"(hi) : "l"(a));
}
__device__ __forceinline__ float tanhap(float x) {
    float r; asm("tanh.approx.f32 %0, %1;" : "=f"(r) : "f"(x)); return r;
}
__device__ __forceinline__ float sigap(float x) {   // exact identity, approx tanh
    return fmaf(tanhap(0.5f * x), 0.5f, 0.5f);
}

// SMEM (floats): Wt[96][96] gate-innermost (kc = k*4+g), Ut[96][24] transposed
//   u rows: [0,24)=aX, [24,48)=X, [48,72)=aH, [72,96)=h ; btot[96]
#define SM_WT 0
#define SM_UT (96*96)
#define SM_B  (SM_UT + 96*24)
#define SM1_FLOATS (SM_B + 96)

__global__ void __launch_bounds__(NT1)
rec_kernel(const float* __restrict__ src, const float* __restrict__ tgt,
           const float* __restrict__ encW, const float* __restrict__ encB,
           const float* __restrict__ xWl, const float* __restrict__ xWr,
           const float* __restrict__ xb,
           const float* __restrict__ hWl, const float* __restrict__ hWr,
           const float* __restrict__ hb,
           const float* __restrict__ gw, const float* __restrict__ gb)
{
    extern __shared__ float sm[];
    float* Wt   = sm + SM_WT;
    float* Ut   = sm + SM_UT;
    float* btot = sm + SM_B;

    const int tid = threadIdx.x;
    const int n   = blockIdx.x;

    // ---- stage combined weights, gate-innermost: Wt[i][k*4+g] = W_g[k][i'] ----
    for (int e = tid; e < 96*96; e += NT1) {
        int i = e / 96, kc = e % 96;
        int k = kc >> 2, g = kc & 3;
        float v;
        if      (i < 24) v = xWl[g*576 + k*24 + i];
        else if (i < 48) v = xWr[g*576 + k*24 + (i-24)];
        else if (i < 72) v = hWl[g*576 + k*24 + (i-48)];
        else             v = hWr[g*576 + k*24 + (i-72)];
        Wt[e] = v;
    }
    for (int e = tid; e < 96; e += NT1) {
        int k = e >> 2, g = e & 3;
        btot[e] = xb[g*24 + k] + hb[g*24 + k] + gb[g*24 + k];
    }

    // ---- init: X = relu(enc(src[n, TSRC-WARM])) (transposed layout), h = 0 ----
    #pragma unroll
    for (int r = 0; r < 6; r++) {
        int e = r*NT1 + tid; int j = e / 24, h = e % 24;
        const float* x = src + (size_t)n*(TSRC*72) + (TSRC-WARM)*72 + j*3;
        float v = encB[h] + x[0]*encW[h*3+0] + x[1]*encW[h*3+1] + x[2]*encW[h*3+2];
        Ut[(24+h)*24 + j] = fmaxf(v, 0.f);
        Ut[(72+h)*24 + j] = 0.f;
    }
    __syncthreads();

    const int jt = tid / 24;           // joints jt*6 .. jt*6+5 (3 pairs)
    const int kt = tid % 24;           // hidden unit k (all 4 gates)
    const float gw0 = gw[kt], gw1 = gw[24+kt], gw2 = gw[48+kt];
    float4 b4 = *(const float4*)(btot + kt*4);
    const ull bs0 = splat2(b4.x), bs1 = splat2(b4.y),
              bs2 = splat2(b4.z), bs3 = splat2(b4.w);

    const float* wp = Wt + kt*4;
    const float* up = Ut + jt*6;
    float c6[6] = {0.f,0.f,0.f,0.f,0.f,0.f};

    for (int t = 0; t < WARM + TOUT; t++) {
        // ---- mean neighbor aggregation: aX(rows 0-23) <- X, aH(48-71) <- h ----
        #pragma unroll
        for (int r = 0; r < 12; r++) {
            int task = r*NT1 + tid;
            int typ = task >= 576;
            int e = task - typ*576;
            int h = e / 24, j = e % 24;
            const float* row = Ut + ((typ ? 72 : 24) + h)*24;
            float s = 0.f;
            int cnt = c_cnt[j];
            #pragma unroll
            for (int m = 0; m < 5; m++)
                if (m < cnt) s += row[c_nbr[j][m]];
            Ut[((typ ? 48 : 0) + h)*24 + j] = s * c_inv[j];
        }
        __syncthreads();

        // ---- packed matvec: S[jpair][g] += Wt[i][kt*4+g] * u[i][jpair] ----
        ull A00=bs0, A01=bs1, A02=bs2, A03=bs3;
        ull A10=bs0, A11=bs1, A12=bs2, A13=bs3;
        ull A20=bs0, A21=bs1, A22=bs2, A23=bs3;
        #pragma unroll 6
        for (int i = 0; i < 96; i++) {
            float4 w = *(const float4*)(wp + i*96);
            ull w0 = splat2(w.x), w1 = splat2(w.y),
                w2 = splat2(w.z), w3 = splat2(w.w);
            ull u0 = *(const ull*)(up + i*24 + 0);
            ull u1 = *(const ull*)(up + i*24 + 2);
            ull u2 = *(const ull*)(up + i*24 + 4);
            A00 = fma2(u0, w0, A00); A01 = fma2(u0, w1, A01);
            A02 = fma2(u0, w2, A02); A03 = fma2(u0, w3, A03);
            A10 = fma2(u1, w0, A10); A11 = fma2(u1, w1, A11);
            A12 = fma2(u1, w2, A12); A13 = fma2(u1, w3, A13);
            A20 = fma2(u2, w0, A20); A21 = fma2(u2, w1, A21);
            A22 = fma2(u2, w2, A22); A23 = fma2(u2, w3, A23);
        }

        // ---- LSTM gates entirely in registers (c never leaves regs) ----
        float s0[6], s1[6], s2[6], s3[6];
        unpack2(A00, s0[0], s0[1]); unpack2(A10, s0[2], s0[3]); unpack2(A20, s0[4], s0[5]);
        unpack2(A01, s1[0], s1[1]); unpack2(A11, s1[2], s1[3]); unpack2(A21, s1[4], s1[5]);
        unpack2(A02, s2[0], s2[1]); unpack2(A12, s2[2], s2[3]); unpack2(A22, s2[4], s2[5]);
        unpack2(A03, s3[0], s3[1]); unpack2(A13, s3[2], s3[3]); unpack2(A23, s3[4], s3[5]);
        float o6[6], h6[6];
        #pragma unroll
        for (int q = 0; q < 6; q++) {
            float c  = c6[q];
            float ig = sigap(fmaf(gw0, c, s0[q]));
            float fg = sigap(fmaf(gw1, c, s1[q]));
            float c2 = fmaf(fg, c, ig * tanhap(s2[q]));
            float og = sigap(fmaf(gw2, c2, s3[q]));
            c6[q] = c2;
            o6[q] = og;
            h6[q] = og * tanhap(c2);
        }
        __syncthreads();   // all matvec reads of Ut complete before overwrite

        float* xrow = Ut + (24+kt)*24 + jt*6;
        float* hrow = Ut + (72+kt)*24 + jt*6;
        *(float2*)(xrow+0) = make_float2(o6[0], o6[1]);
        *(float2*)(xrow+2) = make_float2(o6[2], o6[3]);
        *(float2*)(xrow+4) = make_float2(o6[4], o6[5]);
        *(float2*)(hrow+0) = make_float2(h6[0], h6[1]);
        *(float2*)(hrow+2) = make_float2(h6[2], h6[3]);
        *(float2*)(hrow+4) = make_float2(h6[4], h6[5]);
        __syncthreads();

        if (t == WARM - 1) {
            // transition: X <- relu(enc(tgt[n,0])); h/c carried
            #pragma unroll
            for (int r = 0; r < 6; r++) {
                int e = r*NT1 + tid; int j = e / 24, h = e % 24;
                const float* x = tgt + (size_t)n*(TOUT*72) + j*3;
                float v = encB[h] + x[0]*encW[h*3+0] + x[1]*encW[h*3+1] + x[2]*encW[h*3+2];
                Ut[(24+h)*24 + j] = fmaxf(v, 0.f);
            }
            __syncthreads();
        }
        if (t >= WARM) {
            // coalesced store of o (X row) to g_O[n][t-WARM][j*24+h]
            float* dst = g_O + ((size_t)n*TOUT + (t - WARM))*576;
            #pragma unroll
            for (int r = 0; r < 6; r++) {
                int e = r*NT1 + tid;
                dst[e] = Ut[(24 + (e % 24))*24 + (e / 24)];
            }
            // next writers of these rows are >=1 sync away; reads race-free
        }
    }
}

// ---------------- decoder GEMM: out[65536][72] = O[R][576] @ decW^T + b ----
#define DK 96
__global__ void __launch_bounds__(NT2)
dec_kernel(const float* __restrict__ decW, const float* __restrict__ decB,
           float* __restrict__ out)
{
    extern __shared__ float sm[];
    float* Ot = sm;               // [64][96]
    float* Ws = sm + 64*DK;       // [96][72], k-major

    const int tid  = threadIdx.x;
    const int rowg = tid / 24;
    const int colg = tid % 24;
    const size_t row0 = (size_t)blockIdx.x * 64;

    float acc[8][3];
    #pragma unroll
    for (int rr = 0; rr < 8; rr++)
        #pragma unroll
        for (int cc = 0; cc < 3; cc++) acc[rr][cc] = 0.f;

    for (int kc = 0; kc < 576/DK; kc++) {
        for (int e = tid; e < 64*DK/4; e += NT2) {
            int rr = e / (DK/4), kq = e % (DK/4);
            ((float4*)Ot)[rr*(DK/4) + kq] =
                ((const float4*)(g_O + (row0+rr)*576 + kc*DK))[kq];
        }
        for (int e = tid; e < 72*DK; e += NT2) {
            int c = e / DK, k = e % DK;
            Ws[k*72 + c] = decW[(size_t)c*576 + kc*DK + k];
        }
        __syncthreads();

        #pragma unroll 6
        for (int kq = 0; kq < DK/4; kq++) {
            float w[3][4];
            #pragma unroll
            for (int kk = 0; kk < 4; kk++)
                #pragma unroll
                for (int cc = 0; cc < 3; cc++)
                    w[cc][kk] = Ws[(kq*4+kk)*72 + colg*3 + cc];
            #pragma unroll
            for (int rr = 0; rr < 8; rr++) {
                float4 o = ((const float4*)Ot)[(rowg*8+rr)*(DK/4) + kq];
                #pragma unroll
                for (int cc = 0; cc < 3; cc++)
                    acc[rr][cc] = fmaf(o.x, w[cc][0],
                                  fmaf(o.y, w[cc][1],
                                  fmaf(o.z, w[cc][2],
                                  fmaf(o.w, w[cc][3], acc[rr][cc]))));
            }
        }
        __syncthreads();
    }

    #pragma unroll
    for (int rr = 0; rr < 8; rr++)
        #pragma unroll
        for (int cc = 0; cc < 3; cc++)
            out[(row0 + rowg*8 + rr)*72 + colg*3 + cc] =
                acc[rr][cc] + decB[colg*3 + cc];
}

extern "C" void kernel_launch(void* const* d_in, const int* in_sizes, int n_in,
                              void* d_out, int out_size)
{
    const float* src  = (const float*)d_in[0];
    const float* tgt  = (const float*)d_in[1];
    const float* encW = (const float*)d_in[2];
    const float* encB = (const float*)d_in[3];
    const float* xWl  = (const float*)d_in[4];
    const float* xWr  = (const float*)d_in[5];
    const float* xb   = (const float*)d_in[6];
    const float* hWl  = (const float*)d_in[7];
    const float* hWr  = (const float*)d_in[8];
    const float* hb   = (const float*)d_in[9];
    const float* gw   = (const float*)d_in[10];
    const float* gb   = (const float*)d_in[11];
    const float* decW = (const float*)d_in[12];
    const float* decB = (const float*)d_in[13];
    float* out = (float*)d_out;

    const int smem1 = SM1_FLOATS * 4;          // ~46.5 KB
    const int smem2 = (64*DK + 72*DK) * 4;     // ~52 KB
    cudaFuncSetAttribute(rec_kernel, cudaFuncAttributeMaxDynamicSharedMemorySize, smem1);
    cudaFuncSetAttribute(dec_kernel, cudaFuncAttributeMaxDynamicSharedMemorySize, smem2);

    rec_kernel<<<NBATCH, NT1, smem1>>>(src, tgt, encW, encB,
                                       xWl, xWr, xb, hWl, hWr, hb, gw, gb);
    dec_kernel<<<(NBATCH*TOUT)/64, NT2, smem2>>>(decW, decB, out);
}

// round 5
// speedup vs baseline: 2.0911x; 2.0911x over previous
#include <cuda_runtime.h>
#include <math.h>

// ---------------- problem constants ----------------
#define NBATCH 1024
#define TSRC   32
#define TOUT   64
#define WARM   24
#define NT1    192     // rec threads: 8 j-groups (3 joints) x 24 k
#define NT2    192     // dec threads

// staging buffer for decode outputs o: [N, T, J*H]
__device__ float g_O[(size_t)NBATCH * TOUT * 576];

// SMPL tree adjacency incl. self-loop
__constant__ int c_nbr[24][5] = {
    {0,1,2,3,-1},{1,0,4,-1,-1},{2,0,5,-1,-1},{3,0,6,-1,-1},
    {4,1,7,-1,-1},{5,2,8,-1,-1},{6,3,9,-1,-1},{7,4,10,-1,-1},
    {8,5,11,-1,-1},{9,6,12,13,14},{10,7,-1,-1,-1},{11,8,-1,-1,-1},
    {12,9,15,-1,-1},{13,9,16,-1,-1},{14,9,17,-1,-1},{15,12,-1,-1,-1},
    {16,13,18,-1,-1},{17,14,19,-1,-1},{18,16,20,-1,-1},{19,17,21,-1,-1},
    {20,18,22,-1,-1},{21,19,23,-1,-1},{22,20,-1,-1,-1},{23,21,-1,-1,-1}};
__constant__ int c_cnt[24] = {4,3,3,3, 3,3,3,3, 3,5,2,2, 3,3,3,2, 3,3,3,3, 3,3,2,2};
__constant__ float c_inv[24] = {
    1.f/4,1.f/3,1.f/3,1.f/3, 1.f/3,1.f/3,1.f/3,1.f/3,
    1.f/3,1.f/5,1.f/2,1.f/2, 1.f/3,1.f/3,1.f/3,1.f/2,
    1.f/3,1.f/3,1.f/3,1.f/3, 1.f/3,1.f/3,1.f/2,1.f/2};

// ---- HW tanh approx (MUFU); sigmoid via exact identity ----
__device__ __forceinline__ float tanhap(float x) {
    float r; asm("tanh.approx.f32 %0, %1;" : "=f"(r) : "f"(x)); return r;
}
__device__ __forceinline__ float sigap(float x) {
    return fmaf(tanhap(0.5f * x), 0.5f, 0.5f);
}

#define ACCROW(A, U_) \
    A.x = fmaf(U_.x,w0.x, fmaf(U_.y,w1.x, fmaf(U_.z,w2.x, fmaf(U_.w,w3.x, A.x)))); \
    A.y = fmaf(U_.x,w0.y, fmaf(U_.y,w1.y, fmaf(U_.z,w2.y, fmaf(U_.w,w3.y, A.y)))); \
    A.z = fmaf(U_.x,w0.z, fmaf(U_.y,w1.z, fmaf(U_.z,w2.z, fmaf(U_.w,w3.z, A.z)))); \
    A.w = fmaf(U_.x,w0.w, fmaf(U_.y,w1.w, fmaf(U_.z,w2.w, fmaf(U_.w,w3.w, A.w))));

// SMEM (floats): Wt[96][96] gate-innermost (kc = k*4+g); U[24][96] per-joint
//   u columns: [0,24)=aX, [24,48)=X, [48,72)=aH, [72,96)=h
#define SM_WT 0
#define SM_U  (96*96)
#define SM1_FLOATS (SM_U + 24*96)

__global__ void __launch_bounds__(NT1)
rec_kernel(const float* __restrict__ src, const float* __restrict__ tgt,
           const float* __restrict__ encW, const float* __restrict__ encB,
           const float* __restrict__ xWl, const float* __restrict__ xWr,
           const float* __restrict__ xb,
           const float* __restrict__ hWl, const float* __restrict__ hWr,
           const float* __restrict__ hb,
           const float* __restrict__ gw, const float* __restrict__ gb)
{
    extern __shared__ float sm[];
    float* Wt = sm + SM_WT;
    float* U  = sm + SM_U;

    const int tid = threadIdx.x;
    const int n   = blockIdx.x;

    // ---- stage combined weights, gate-innermost: Wt[i][k*4+g] = W_g[k][i'] ----
    for (int e = tid; e < 96*96; e += NT1) {
        int i = e / 96, kc = e % 96;
        int k = kc >> 2, g = kc & 3;
        float v;
        if      (i < 24) v = xWl[g*576 + k*24 + i];
        else if (i < 48) v = xWr[g*576 + k*24 + (i-24)];
        else if (i < 72) v = hWl[g*576 + k*24 + (i-48)];
        else             v = hWr[g*576 + k*24 + (i-72)];
        Wt[e] = v;
    }

    // ---- init: X = relu(enc(src[n, TSRC-WARM])), h = 0 ----
    #pragma unroll
    for (int r = 0; r < 3; r++) {
        int e = r*NT1 + tid; int j = e/24, h = e%24;
        const float* x = src + (size_t)n*(TSRC*72) + (TSRC-WARM)*72 + j*3;
        float v = encB[h] + x[0]*encW[h*3+0] + x[1]*encW[h*3+1] + x[2]*encW[h*3+2];
        U[j*96 + 24 + h] = fmaxf(v, 0.f);
        U[j*96 + 72 + h] = 0.f;
    }
    __syncthreads();

    const int jt = tid / 24;           // joints jt*3 .. jt*3+2
    const int kt = tid % 24;           // hidden unit k (all 4 gates)
    // per-thread constants in registers
    const float gw0 = gw[kt], gw1 = gw[24+kt], gw2 = gw[48+kt];
    float4 bq;
    bq.x = xb[      kt] + hb[      kt] + gb[      kt];   // gate i
    bq.y = xb[24 + kt] + hb[24 + kt] + gb[24 + kt];      // gate f
    bq.z = xb[48 + kt] + hb[48 + kt] + gb[48 + kt];      // gate c
    bq.w = xb[72 + kt] + hb[72 + kt] + gb[72 + kt];      // gate o

    const float4* W4 = (const float4*)Wt;    // W4[i*24 + kt] = Wt[i][kt*4..+3]
    const float*  Uj = U + jt*3*96;
    float c3[3] = {0.f, 0.f, 0.f};

    for (int t = 0; t < WARM + TOUT; t++) {
        // ---- mean neighbor aggregation: aX <- X, aH <- h ----
        #pragma unroll
        for (int r = 0; r < 6; r++) {
            int task = r*NT1 + tid;
            int typ = task >= 576;
            int e = task - typ*576;
            int j = e/24, h = e%24;
            int so = typ ? 72 : 24, dof = typ ? 48 : 0;
            float s = 0.f;
            int cnt = c_cnt[j];
            #pragma unroll
            for (int m = 0; m < 5; m++)
                if (m < cnt) s += U[c_nbr[j][m]*96 + so + h];
            U[j*96 + dof + h] = s * c_inv[j];
        }
        __syncthreads();

        // ---- matvec: a_r = (Si,Sf,Sc,So) for joint jt*3+r, hidden unit kt ----
        float4 a0 = bq, a1 = bq, a2 = bq;
        #pragma unroll 8
        for (int iq = 0; iq < 24; iq++) {
            float4 ua = ((const float4*)(Uj      ))[iq];
            float4 ub = ((const float4*)(Uj +  96))[iq];
            float4 uc = ((const float4*)(Uj + 192))[iq];
            float4 w0 = W4[(iq*4+0)*24 + kt];
            float4 w1 = W4[(iq*4+1)*24 + kt];
            float4 w2 = W4[(iq*4+2)*24 + kt];
            float4 w3 = W4[(iq*4+3)*24 + kt];
            ACCROW(a0, ua)
            ACCROW(a1, ub)
            ACCROW(a2, uc)
        }

        // ---- LSTM gates in registers (c never leaves regs) ----
        float o3[3], h3[3];
        {
            float4 s;
            #pragma unroll
            for (int r = 0; r < 3; r++) {
                s = (r == 0) ? a0 : (r == 1) ? a1 : a2;
                float c  = c3[r];
                float ig = sigap(fmaf(gw0, c, s.x));
                float fg = sigap(fmaf(gw1, c, s.y));
                float c2 = fmaf(fg, c, ig * tanhap(s.z));
                float og = sigap(fmaf(gw2, c2, s.w));
                c3[r] = c2;
                o3[r] = og;
                h3[r] = og * tanhap(c2);
            }
        }
        __syncthreads();   // all matvec reads of U complete before overwrite

        #pragma unroll
        for (int r = 0; r < 3; r++) {
            U[(jt*3+r)*96 + 24 + kt] = o3[r];   // X_{t+1} = o_t
            U[(jt*3+r)*96 + 72 + kt] = h3[r];
        }
        __syncthreads();

        if (t == WARM - 1) {
            // transition: X <- relu(enc(tgt[n,0])); h/c carried
            #pragma unroll
            for (int r = 0; r < 3; r++) {
                int e = r*NT1 + tid; int j = e/24, h = e%24;
                const float* x = tgt + (size_t)n*(TOUT*72) + j*3;
                float v = encB[h] + x[0]*encW[h*3+0] + x[1]*encW[h*3+1] + x[2]*encW[h*3+2];
                U[j*96 + 24 + h] = fmaxf(v, 0.f);
            }
            __syncthreads();
        }
        if (t >= WARM) {
            // coalesced store of o to g_O[n][t-WARM][j*24+h]
            float* dst = g_O + ((size_t)n*TOUT + (t - WARM))*576;
            #pragma unroll
            for (int r = 0; r < 3; r++) {
                int e = r*NT1 + tid;
                dst[e] = U[(e/24)*96 + 24 + (e%24)];
            }
        }
    }
}

// ---------------- decoder GEMM: out[65536][72] = O[R][576] @ decW^T + b ----
#define DK 96
__global__ void __launch_bounds__(NT2)
dec_kernel(const float* __restrict__ decW, const float* __restrict__ decB,
           float* __restrict__ out)
{
    extern __shared__ float sm[];
    float* Ot = sm;               // [64][96]
    float* Ws = sm + 64*DK;       // [96][72], k-major

    const int tid  = threadIdx.x;
    const int rowg = tid / 24;
    const int colg = tid % 24;
    const size_t row0 = (size_t)blockIdx.x * 64;

    float acc[8][3];
    #pragma unroll
    for (int rr = 0; rr < 8; rr++)
        #pragma unroll
        for (int cc = 0; cc < 3; cc++) acc[rr][cc] = 0.f;

    for (int kc = 0; kc < 576/DK; kc++) {
        for (int e = tid; e < 64*DK/4; e += NT2) {
            int rr = e / (DK/4), kq = e % (DK/4);
            ((float4*)Ot)[rr*(DK/4) + kq] =
                ((const float4*)(g_O + (row0+rr)*576 + kc*DK))[kq];
        }
        for (int e = tid; e < 72*DK; e += NT2) {
            int c = e / DK, k = e % DK;
            Ws[k*72 + c] = decW[(size_t)c*576 + kc*DK + k];
        }
        __syncthreads();

        #pragma unroll 6
        for (int kq = 0; kq < DK/4; kq++) {
            float w[3][4];
            #pragma unroll
            for (int kk = 0; kk < 4; kk++)
                #pragma unroll
                for (int cc = 0; cc < 3; cc++)
                    w[cc][kk] = Ws[(kq*4+kk)*72 + colg*3 + cc];
            #pragma unroll
            for (int rr = 0; rr < 8; rr++) {
                float4 o = ((const float4*)Ot)[(rowg*8+rr)*(DK/4) + kq];
                #pragma unroll
                for (int cc = 0; cc < 3; cc++)
                    acc[rr][cc] = fmaf(o.x, w[cc][0],
                                  fmaf(o.y, w[cc][1],
                                  fmaf(o.z, w[cc][2],
                                  fmaf(o.w, w[cc][3], acc[rr][cc]))));
            }
        }
        __syncthreads();
    }

    #pragma unroll
    for (int rr = 0; rr < 8; rr++)
        #pragma unroll
        for (int cc = 0; cc < 3; cc++)
            out[(row0 + rowg*8 + rr)*72 + colg*3 + cc] =
                acc[rr][cc] + decB[colg*3 + cc];
}

extern "C" void kernel_launch(void* const* d_in, const int* in_sizes, int n_in,
                              void* d_out, int out_size)
{
    const float* src  = (const float*)d_in[0];
    const float* tgt  = (const float*)d_in[1];
    const float* encW = (const float*)d_in[2];
    const float* encB = (const float*)d_in[3];
    const float* xWl  = (const float*)d_in[4];
    const float* xWr  = (const float*)d_in[5];
    const float* xb   = (const float*)d_in[6];
    const float* hWl  = (const float*)d_in[7];
    const float* hWr  = (const float*)d_in[8];
    const float* hb   = (const float*)d_in[9];
    const float* gw   = (const float*)d_in[10];
    const float* gb   = (const float*)d_in[11];
    const float* decW = (const float*)d_in[12];
    const float* decB = (const float*)d_in[13];
    float* out = (float*)d_out;

    const int smem1 = SM1_FLOATS * 4;          // ~45.9 KB
    const int smem2 = (64*DK + 72*DK) * 4;     // ~52 KB
    cudaFuncSetAttribute(rec_kernel, cudaFuncAttributeMaxDynamicSharedMemorySize, smem1);
    cudaFuncSetAttribute(dec_kernel, cudaFuncAttributeMaxDynamicSharedMemorySize, smem2);

    rec_kernel<<<NBATCH, NT1, smem1>>>(src, tgt, encW, encB,
                                       xWl, xWr, xb, hWl, hWr, hb, gw, gb);
    dec_kernel<<<(NBATCH*TOUT)/64, NT2, smem2>>>(decW, decB, out);
}

// round 6
// speedup vs baseline: 2.1001x; 1.0043x over previous
#include <cuda_runtime.h>
#include <math.h>

// ---------------- problem constants ----------------
#define NBATCH 1024
#define TSRC   32
#define TOUT   64
#define WARM   24
#define NT1    192     // rec threads: 8 j-groups (3 joints) x 24 k
#define NT2    192     // dec threads

// staging buffer for decode outputs o: [N, T, J*H]
__device__ float g_O[(size_t)NBATCH * TOUT * 576];

// SMPL tree adjacency incl. self-loop
__constant__ int c_nbr[24][5] = {
    {0,1,2,3,-1},{1,0,4,-1,-1},{2,0,5,-1,-1},{3,0,6,-1,-1},
    {4,1,7,-1,-1},{5,2,8,-1,-1},{6,3,9,-1,-1},{7,4,10,-1,-1},
    {8,5,11,-1,-1},{9,6,12,13,14},{10,7,-1,-1,-1},{11,8,-1,-1,-1},
    {12,9,15,-1,-1},{13,9,16,-1,-1},{14,9,17,-1,-1},{15,12,-1,-1,-1},
    {16,13,18,-1,-1},{17,14,19,-1,-1},{18,16,20,-1,-1},{19,17,21,-1,-1},
    {20,18,22,-1,-1},{21,19,23,-1,-1},{22,20,-1,-1,-1},{23,21,-1,-1,-1}};
__constant__ int c_cnt[24] = {4,3,3,3, 3,3,3,3, 3,5,2,2, 3,3,3,2, 3,3,3,3, 3,3,2,2};
__constant__ float c_inv[24] = {
    1.f/4,1.f/3,1.f/3,1.f/3, 1.f/3,1.f/3,1.f/3,1.f/3,
    1.f/3,1.f/5,1.f/2,1.f/2, 1.f/3,1.f/3,1.f/3,1.f/2,
    1.f/3,1.f/3,1.f/3,1.f/3, 1.f/3,1.f/3,1.f/2,1.f/2};

// ---- HW tanh approx (MUFU); sigmoid via exact identity ----
__device__ __forceinline__ float tanhap(float x) {
    float r; asm("tanh.approx.f32 %0, %1;" : "=f"(r) : "f"(x)); return r;
}
__device__ __forceinline__ float sigap(float x) {
    return fmaf(tanhap(0.5f * x), 0.5f, 0.5f);
}

#define ACCROW(A, U_) \
    A.x = fmaf(U_.x,w0.x, fmaf(U_.y,w1.x, fmaf(U_.z,w2.x, fmaf(U_.w,w3.x, A.x)))); \
    A.y = fmaf(U_.x,w0.y, fmaf(U_.y,w1.y, fmaf(U_.z,w2.y, fmaf(U_.w,w3.y, A.y)))); \
    A.z = fmaf(U_.x,w0.z, fmaf(U_.y,w1.z, fmaf(U_.z,w2.z, fmaf(U_.w,w3.z, A.z)))); \
    A.w = fmaf(U_.x,w0.w, fmaf(U_.y,w1.w, fmaf(U_.z,w2.w, fmaf(U_.w,w3.w, A.w))));

// SMEM (floats): Wt[96][96] gate-innermost (kc = k*4+g); U[24][96] per-joint
//   u columns: [0,24)=aX, [24,48)=X, [48,72)=aH, [72,96)=h
#define SM_WT 0
#define SM_U  (96*96)
#define SM1_FLOATS (SM_U + 24*96)

__global__ void __launch_bounds__(NT1)
rec_kernel(const float* __restrict__ src, const float* __restrict__ tgt,
           const float* __restrict__ encW, const float* __restrict__ encB,
           const float* __restrict__ xWl, const float* __restrict__ xWr,
           const float* __restrict__ xb,
           const float* __restrict__ hWl, const float* __restrict__ hWr,
           const float* __restrict__ hb,
           const float* __restrict__ gw, const float* __restrict__ gb)
{
    extern __shared__ float sm[];
    float* Wt = sm + SM_WT;
    float* U  = sm + SM_U;

    const int tid = threadIdx.x;
    const int n   = blockIdx.x;

    // ---- stage combined weights, gate-innermost: Wt[i][k*4+g] = W_g[k][i'] ----
    for (int e = tid; e < 96*96; e += NT1) {
        int i = e / 96, kc = e % 96;
        int k = kc >> 2, g = kc & 3;
        float v;
        if      (i < 24) v = xWl[g*576 + k*24 + i];
        else if (i < 48) v = xWr[g*576 + k*24 + (i-24)];
        else if (i < 72) v = hWl[g*576 + k*24 + (i-48)];
        else             v = hWr[g*576 + k*24 + (i-72)];
        Wt[e] = v;
    }

    // ---- init: X = relu(enc(src[n, TSRC-WARM])), h = 0 ----
    #pragma unroll
    for (int r = 0; r < 3; r++) {
        int e = r*NT1 + tid; int j = e/24, h = e%24;
        const float* x = src + (size_t)n*(TSRC*72) + (TSRC-WARM)*72 + j*3;
        float v = encB[h] + x[0]*encW[h*3+0] + x[1]*encW[h*3+1] + x[2]*encW[h*3+2];
        U[j*96 + 24 + h] = fmaxf(v, 0.f);
        U[j*96 + 72 + h] = 0.f;
    }
    __syncthreads();

    const int jt = tid / 24;           // joints jt*3 .. jt*3+2
    const int kt = tid % 24;           // hidden unit k (all 4 gates)
    // per-thread constants in registers
    const float gw0 = gw[kt], gw1 = gw[24+kt], gw2 = gw[48+kt];
    float4 bq;
    bq.x = xb[      kt] + hb[      kt] + gb[      kt];   // gate i
    bq.y = xb[24 + kt] + hb[24 + kt] + gb[24 + kt];      // gate f
    bq.z = xb[48 + kt] + hb[48 + kt] + gb[48 + kt];      // gate c
    bq.w = xb[72 + kt] + hb[72 + kt] + gb[72 + kt];      // gate o

    const float4* W4 = (const float4*)Wt;    // W4[i*24 + kt] = Wt[i][kt*4..+3]
    const float*  Uj = U + jt*3*96;
    float c3[3] = {0.f, 0.f, 0.f};

    for (int t = 0; t < WARM + TOUT; t++) {
        // ---- mean neighbor aggregation: aX <- X, aH <- h ----
        #pragma unroll
        for (int r = 0; r < 6; r++) {
            int task = r*NT1 + tid;
            int typ = task >= 576;
            int e = task - typ*576;
            int j = e/24, h = e%24;
            int so = typ ? 72 : 24, dof = typ ? 48 : 0;
            float s = 0.f;
            int cnt = c_cnt[j];
            #pragma unroll
            for (int m = 0; m < 5; m++)
                if (m < cnt) s += U[c_nbr[j][m]*96 + so + h];
            U[j*96 + dof + h] = s * c_inv[j];
        }
        __syncthreads();

        // ---- matvec: a_r = (Si,Sf,Sc,So) for joint jt*3+r, hidden unit kt ----
        float4 a0 = bq, a1 = bq, a2 = bq;
        #pragma unroll 8
        for (int iq = 0; iq < 24; iq++) {
            float4 ua = ((const float4*)(Uj      ))[iq];
            float4 ub = ((const float4*)(Uj +  96))[iq];
            float4 uc = ((const float4*)(Uj + 192))[iq];
            float4 w0 = W4[(iq*4+0)*24 + kt];
            float4 w1 = W4[(iq*4+1)*24 + kt];
            float4 w2 = W4[(iq*4+2)*24 + kt];
            float4 w3 = W4[(iq*4+3)*24 + kt];
            ACCROW(a0, ua)
            ACCROW(a1, ub)
            ACCROW(a2, uc)
        }

        // ---- LSTM gates in registers (c never leaves regs) ----
        float o3[3], h3[3];
        {
            float4 s;
            #pragma unroll
            for (int r = 0; r < 3; r++) {
                s = (r == 0) ? a0 : (r == 1) ? a1 : a2;
                float c  = c3[r];
                float ig = sigap(fmaf(gw0, c, s.x));
                float fg = sigap(fmaf(gw1, c, s.y));
                float c2 = fmaf(fg, c, ig * tanhap(s.z));
                float og = sigap(fmaf(gw2, c2, s.w));
                c3[r] = c2;
                o3[r] = og;
                h3[r] = og * tanhap(c2);
            }
        }
        __syncthreads();   // all matvec reads of U complete before overwrite

        #pragma unroll
        for (int r = 0; r < 3; r++) {
            U[(jt*3+r)*96 + 24 + kt] = o3[r];   // X_{t+1} = o_t
            U[(jt*3+r)*96 + 72 + kt] = h3[r];
        }
        __syncthreads();

        if (t == WARM - 1) {
            // transition: X <- relu(enc(tgt[n,0])); h/c carried
            #pragma unroll
            for (int r = 0; r < 3; r++) {
                int e = r*NT1 + tid; int j = e/24, h = e%24;
                const float* x = tgt + (size_t)n*(TOUT*72) + j*3;
                float v = encB[h] + x[0]*encW[h*3+0] + x[1]*encW[h*3+1] + x[2]*encW[h*3+2];
                U[j*96 + 24 + h] = fmaxf(v, 0.f);
            }
            __syncthreads();
        }
        if (t >= WARM) {
            // coalesced store of o to g_O[n][t-WARM][j*24+h]
            float* dst = g_O + ((size_t)n*TOUT + (t - WARM))*576;
            #pragma unroll
            for (int r = 0; r < 3; r++) {
                int e = r*NT1 + tid;
                dst[e] = U[(e/24)*96 + 24 + (e%24)];
            }
        }
    }
}

// ---------------- decoder GEMM: out[65536][72] = O[R][576] @ decW^T + b ----
#define DK 96
__global__ void __launch_bounds__(NT2)
dec_kernel(const float* __restrict__ decW, const float* __restrict__ decB,
           float* __restrict__ out)
{
    extern __shared__ float sm[];
    float* Ot = sm;               // [64][96]
    float* Ws = sm + 64*DK;       // [96][72], k-major

    const int tid  = threadIdx.x;
    const int rowg = tid / 24;
    const int colg = tid % 24;
    const size_t row0 = (size_t)blockIdx.x * 64;

    float acc[8][3];
    #pragma unroll
    for (int rr = 0; rr < 8; rr++)
        #pragma unroll
        for (int cc = 0; cc < 3; cc++) acc[rr][cc] = 0.f;

    for (int kc = 0; kc < 576/DK; kc++) {
        for (int e = tid; e < 64*DK/4; e += NT2) {
            int rr = e / (DK/4), kq = e % (DK/4);
            ((float4*)Ot)[rr*(DK/4) + kq] =
                ((const float4*)(g_O + (row0+rr)*576 + kc*DK))[kq];
        }
        for (int e = tid; e < 72*DK; e += NT2) {
            int c = e / DK, k = e % DK;
            Ws[k*72 + c] = decW[(size_t)c*576 + kc*DK + k];
        }
        __syncthreads();

        #pragma unroll 6
        for (int kq = 0; kq < DK/4; kq++) {
            float w[3][4];
            #pragma unroll
            for (int kk = 0; kk < 4; kk++)
                #pragma unroll
                for (int cc = 0; cc < 3; cc++)
                    w[cc][kk] = Ws[(kq*4+kk)*72 + colg*3 + cc];
            #pragma unroll
            for (int rr = 0; rr < 8; rr++) {
                float4 o = ((const float4*)Ot)[(rowg*8+rr)*(DK/4) + kq];
                #pragma unroll
                for (int cc = 0; cc < 3; cc++)
                    acc[rr][cc] = fmaf(o.x, w[cc][0],
                                  fmaf(o.y, w[cc][1],
                                  fmaf(o.z, w[cc][2],
                                  fmaf(o.w, w[cc][3], acc[rr][cc]))));
            }
        }
        __syncthreads();
    }

    #pragma unroll
    for (int rr = 0; rr < 8; rr++)
        #pragma unroll
        for (int cc = 0; cc < 3; cc++)
            out[(row0 + rowg*8 + rr)*72 + colg*3 + cc] =
                acc[rr][cc] + decB[colg*3 + cc];
}

extern "C" void kernel_launch(void* const* d_in, const int* in_sizes, int n_in,
                              void* d_out, int out_size)
{
    const float* src  = (const float*)d_in[0];
    const float* tgt  = (const float*)d_in[1];
    const float* encW = (const float*)d_in[2];
    const float* encB = (const float*)d_in[3];
    const float* xWl  = (const float*)d_in[4];
    const float* xWr  = (const float*)d_in[5];
    const float* xb   = (const float*)d_in[6];
    const float* hWl  = (const float*)d_in[7];
    const float* hWr  = (const float*)d_in[8];
    const float* hb   = (const float*)d_in[9];
    const float* gw   = (const float*)d_in[10];
    const float* gb   = (const float*)d_in[11];
    const float* decW = (const float*)d_in[12];
    const float* decB = (const float*)d_in[13];
    float* out = (float*)d_out;

    const int smem1 = SM1_FLOATS * 4;          // ~45.9 KB
    const int smem2 = (64*DK + 72*DK) * 4;     // ~52 KB
    cudaFuncSetAttribute(rec_kernel, cudaFuncAttributeMaxDynamicSharedMemorySize, smem1);
    cudaFuncSetAttribute(dec_kernel, cudaFuncAttributeMaxDynamicSharedMemorySize, smem2);

    rec_kernel<<<NBATCH, NT1, smem1>>>(src, tgt, encW, encB,
                                       xWl, xWr, xb, hWl, hWr, hb, gw, gb);
    dec_kernel<<<(NBATCH*TOUT)/64, NT2, smem2>>>(decW, decB, out);
}

// round 7
// speedup vs baseline: 3.4340x; 1.6351x over previous
#include <cuda_runtime.h>
#include <cuda_fp16.h>
#include <math.h>
#include <stdint.h>

#define NBATCH 1024
#define TSRC   32
#define TOUT   64
#define WARM   24
#define NT1    192
#define NT2    192

__device__ float g_O[(size_t)NBATCH * TOUT * 576];

__constant__ int c_nbr[24][5] = {
    {0,1,2,3,-1},{1,0,4,-1,-1},{2,0,5,-1,-1},{3,0,6,-1,-1},
    {4,1,7,-1,-1},{5,2,8,-1,-1},{6,3,9,-1,-1},{7,4,10,-1,-1},
    {8,5,11,-1,-1},{9,6,12,13,14},{10,7,-1,-1,-1},{11,8,-1,-1,-1},
    {12,9,15,-1,-1},{13,9,16,-1,-1},{14,9,17,-1,-1},{15,12,-1,-1,-1},
    {16,13,18,-1,-1},{17,14,19,-1,-1},{18,16,20,-1,-1},{19,17,21,-1,-1},
    {20,18,22,-1,-1},{21,19,23,-1,-1},{22,20,-1,-1,-1},{23,21,-1,-1,-1}};
__constant__ int c_cnt[24] = {4,3,3,3, 3,3,3,3, 3,5,2,2, 3,3,3,2, 3,3,3,3, 3,3,2,2};
__constant__ float c_inv[24] = {
    1.f/4,1.f/3,1.f/3,1.f/3, 1.f/3,1.f/3,1.f/3,1.f/3,
    1.f/3,1.f/5,1.f/2,1.f/2, 1.f/3,1.f/3,1.f/3,1.f/2,
    1.f/3,1.f/3,1.f/3,1.f/3, 1.f/3,1.f/3,1.f/2,1.f/2};

__device__ __forceinline__ float tanhap(float x) {
    float r; asm("tanh.approx.f32 %0, %1;" : "=f"(r) : "f"(x)); return r;
}
__device__ __forceinline__ float sigap(float x) {
    return fmaf(tanhap(0.5f * x), 0.5f, 0.5f);
}
__device__ __forceinline__ void mma16816(float* c, const uint32_t* a, const uint32_t* b) {
    asm volatile("mma.sync.aligned.m16n8k16.row.col.f32.f16.f16.f32 "
        "{%0,%1,%2,%3}, {%4,%5,%6,%7}, {%8,%9}, {%0,%1,%2,%3};"
        : "+f"(c[0]), "+f"(c[1]), "+f"(c[2]), "+f"(c[3])
        : "r"(a[0]), "r"(a[1]), "r"(a[2]), "r"(a[3]), "r"(b[0]), "r"(b[1]));
}

// SMEM byte offsets. A/W rows padded to 104 halves (208B) -> conflict-free frags.
#define SA_HI 0                       // half [32][104]
#define SA_LO (SA_HI + 32*104*2)      // 6656
#define SW_HI (SA_LO + 32*104*2)      // 13312, half [96][104]
#define SW_LO (SW_HI + 96*104*2)      // 33280
#define SS    (SW_LO + 96*104*2)      // 53248, float [24][100]
#define SU    (SS + 24*100*4)         // 62848, float [24][48]: X cols 0-23, h 24-47
#define SBT   (SU + 24*48*4)          // 67456, float [96]
#define SGW   (SBT + 96*4)            // 67840, float [72]
#define SMEM1 (SGW + 72*4)            // 68128

__global__ void __launch_bounds__(NT1, 3)
rec_kernel(const float* __restrict__ src, const float* __restrict__ tgt,
           const float* __restrict__ encW, const float* __restrict__ encB,
           const float* __restrict__ xWl, const float* __restrict__ xWr,
           const float* __restrict__ xb,
           const float* __restrict__ hWl, const float* __restrict__ hWr,
           const float* __restrict__ hb,
           const float* __restrict__ gw, const float* __restrict__ gb)
{
    extern __shared__ char smb[];
    __half* Ahi = (__half*)(smb + SA_HI);
    __half* Alo = (__half*)(smb + SA_LO);
    __half* Whi = (__half*)(smb + SW_HI);
    __half* Wlo = (__half*)(smb + SW_LO);
    float*  S   = (float*)(smb + SS);
    float*  U   = (float*)(smb + SU);
    float*  btot= (float*)(smb + SBT);
    float*  gwp = (float*)(smb + SGW);

    const int tid = threadIdx.x;
    const int n   = blockIdx.x;
    const int wid = tid >> 5, lane = tid & 31;
    const int g   = lane >> 2, t2 = (lane & 3) * 2;
    const int nb  = wid * 16;              // this warp's N-column base

    // ---- stage W split: row kc=k*4+g, col i in [aX|X|aH|h] order ----
    for (int e = tid; e < 96*96; e += NT1) {
        int kc = e / 96, i = e % 96;
        int k = kc >> 2, gg = kc & 3;
        float v;
        if      (i < 24) v = xWl[gg*576 + k*24 + i];
        else if (i < 48) v = xWr[gg*576 + k*24 + (i-24)];
        else if (i < 72) v = hWl[gg*576 + k*24 + (i-48)];
        else             v = hWr[gg*576 + k*24 + (i-72)];
        __half hh = __float2half_rn(v);
        Whi[kc*104 + i] = hh;
        Wlo[kc*104 + i] = __float2half_rn(v - __half2float(hh));
    }
    for (int e = tid; e < 96; e += NT1) {
        int k = e >> 2, gg = e & 3;
        btot[e] = xb[gg*24 + k] + hb[gg*24 + k] + gb[gg*24 + k];
    }
    for (int e = tid; e < 72; e += NT1) gwp[e] = gw[e];
    // zero all of A once (covers pad rows 24-31 forever)
    for (int e = tid; e < 32*52; e += NT1) {
        ((uint32_t*)Ahi)[e] = 0u;
        ((uint32_t*)Alo)[e] = 0u;
    }
    // init state: X = relu(enc(src[n, TSRC-WARM])), h = 0
    #pragma unroll
    for (int r = 0; r < 3; r++) {
        int e = r*NT1 + tid; int j = e/24, h = e%24;
        const float* x = src + ((size_t)n*TSRC + (TSRC-WARM))*72 + j*3;
        float v = encB[h] + x[0]*encW[h*3] + x[1]*encW[h*3+1] + x[2]*encW[h*3+2];
        U[j*48 + h]      = fmaxf(v, 0.f);
        U[j*48 + 24 + h] = 0.f;
    }
    __syncthreads();

    const int kth = tid % 24;                       // gate-phase hidden unit
    const float gw0 = gwp[kth], gw1 = gwp[24+kth], gw2 = gwp[48+kth];
    const float4 bq = *(const float4*)&btot[kth*4];
    float c3[3] = {0.f, 0.f, 0.f};

    for (int t = 0; t < WARM + TOUT; t++) {
        // ---- (A) stage A = [aX|X|aH|h] fp16 hi/lo split, pair of cols per task
        #pragma unroll
        for (int r = 0; r < 6; r++) {
            int e = r*NT1 + tid;          // 0..1151
            int j = e / 48, c = (e % 48) * 2;
            int tc = c / 24, kk = c % 24;
            int so = (tc >= 2) ? 24 : 0;
            float x0, x1;
            if (tc & 1) {                 // copy X or h
                float2 u = *(const float2*)&U[j*48 + so + kk];
                x0 = u.x; x1 = u.y;
            } else {                      // mean-aggregate
                x0 = 0.f; x1 = 0.f;
                int cnt = c_cnt[j];
                #pragma unroll
                for (int m = 0; m < 5; m++) if (m < cnt) {
                    float2 u = *(const float2*)&U[c_nbr[j][m]*48 + so + kk];
                    x0 += u.x; x1 += u.y;
                }
                x0 *= c_inv[j]; x1 *= c_inv[j];
            }
            __half2 hi2 = __floats2half2_rn(x0, x1);
            float2 hf = __half22float2(hi2);
            __half2 lo2 = __floats2half2_rn(x0 - hf.x, x1 - hf.y);
            *(__half2*)&Ahi[j*104 + c] = hi2;
            *(__half2*)&Alo[j*104 + c] = lo2;
        }
        __syncthreads();

        // ---- (C) warp MMA: this warp covers N cols [nb, nb+16), all 32 rows
        float cf[2][2][4];
        #pragma unroll
        for (int m = 0; m < 2; m++)
            #pragma unroll
            for (int nn = 0; nn < 2; nn++)
                #pragma unroll
                for (int q = 0; q < 4; q++) cf[m][nn][q] = 0.f;

        #pragma unroll
        for (int kt = 0; kt < 6; kt++) {
            int kb = kt * 16;
            uint32_t ah[2][4], al[2][4], wh[2][2], wl[2][2];
            #pragma unroll
            for (int m = 0; m < 2; m++) {
                int r0 = m*16 + g, r1 = r0 + 8;
                ah[m][0] = *(const uint32_t*)&Ahi[r0*104 + kb + t2];
                ah[m][1] = *(const uint32_t*)&Ahi[r1*104 + kb + t2];
                ah[m][2] = *(const uint32_t*)&Ahi[r0*104 + kb + t2 + 8];
                ah[m][3] = *(const uint32_t*)&Ahi[r1*104 + kb + t2 + 8];
                al[m][0] = *(const uint32_t*)&Alo[r0*104 + kb + t2];
                al[m][1] = *(const uint32_t*)&Alo[r1*104 + kb + t2];
                al[m][2] = *(const uint32_t*)&Alo[r0*104 + kb + t2 + 8];
                al[m][3] = *(const uint32_t*)&Alo[r1*104 + kb + t2 + 8];
            }
            #pragma unroll
            for (int nn = 0; nn < 2; nn++) {
                int nr = nb + nn*8 + g;
                wh[nn][0] = *(const uint32_t*)&Whi[nr*104 + kb + t2];
                wh[nn][1] = *(const uint32_t*)&Whi[nr*104 + kb + t2 + 8];
                wl[nn][0] = *(const uint32_t*)&Wlo[nr*104 + kb + t2];
                wl[nn][1] = *(const uint32_t*)&Wlo[nr*104 + kb + t2 + 8];
            }
            #pragma unroll
            for (int m = 0; m < 2; m++)
                #pragma unroll
                for (int nn = 0; nn < 2; nn++) {
                    mma16816(cf[m][nn], ah[m], wh[nn]);
                    mma16816(cf[m][nn], ah[m], wl[nn]);
                    mma16816(cf[m][nn], al[m], wh[nn]);
                }
        }

        // ---- (D) C frags -> S[24][100]
        #pragma unroll
        for (int m = 0; m < 2; m++)
            #pragma unroll
            for (int nn = 0; nn < 2; nn++) {
                int col = nb + nn*8 + t2;
                int r0 = m*16 + g, r1 = r0 + 8;
                *(float2*)&S[r0*100 + col] = make_float2(cf[m][nn][0], cf[m][nn][1]);
                if (r1 < 24)
                    *(float2*)&S[r1*100 + col] = make_float2(cf[m][nn][2], cf[m][nn][3]);
            }
        __syncthreads();

        // ---- (E) LSTM gates; c in regs; store o,h to U; o to g_O when decoding
        float* dst = g_O + ((size_t)n*TOUT + (t - WARM))*576;
        #pragma unroll
        for (int r = 0; r < 3; r++) {
            int j = r*8 + tid/24;
            float4 s4 = *(const float4*)&S[j*100 + kth*4];
            float c  = c3[r];
            float ig = sigap(fmaf(gw0, c, s4.x + bq.x));
            float fg = sigap(fmaf(gw1, c, s4.y + bq.y));
            float c2 = fmaf(fg, c, ig * tanhap(s4.z + bq.z));
            float og = sigap(fmaf(gw2, c2, s4.w + bq.w));
            c3[r] = c2;
            U[j*48 + kth]      = og;          // X_{t+1} = o_t
            U[j*48 + 24 + kth] = og * tanhap(c2);
            if (t >= WARM) dst[r*192 + tid] = og;   // coalesced: j*24+k == r*192+tid
        }
        __syncthreads();

        if (t == WARM - 1) {    // X <- relu(enc(tgt[n,0])); h/c carried
            #pragma unroll
            for (int r = 0; r < 3; r++) {
                int e = r*NT1 + tid; int j = e/24, h = e%24;
                const float* x = tgt + (size_t)n*(TOUT*72) + j*3;
                float v = encB[h] + x[0]*encW[h*3] + x[1]*encW[h*3+1] + x[2]*encW[h*3+2];
                U[j*48 + h] = fmaxf(v, 0.f);
            }
            __syncthreads();
        }
    }
}

// ---------------- decoder GEMM: out[65536][72] = O[R][576] @ decW^T + b ----
#define DK 96
__global__ void __launch_bounds__(NT2)
dec_kernel(const float* __restrict__ decW, const float* __restrict__ decB,
           float* __restrict__ out)
{
    extern __shared__ float sm[];
    float* Ot = sm;               // [64][96]
    float* Ws = sm + 64*DK;       // [96][72], k-major

    const int tid  = threadIdx.x;
    const int rowg = tid / 24;
    const int colg = tid % 24;
    const size_t row0 = (size_t)blockIdx.x * 64;

    float acc[8][3];
    #pragma unroll
    for (int rr = 0; rr < 8; rr++)
        #pragma unroll
        for (int cc = 0; cc < 3; cc++) acc[rr][cc] = 0.f;

    for (int kc = 0; kc < 576/DK; kc++) {
        for (int e = tid; e < 64*DK/4; e += NT2) {
            int rr = e / (DK/4), kq = e % (DK/4);
            ((float4*)Ot)[rr*(DK/4) + kq] =
                ((const float4*)(g_O + (row0+rr)*576 + kc*DK))[kq];
        }
        for (int e = tid; e < 72*DK; e += NT2) {
            int c = e / DK, k = e % DK;
            Ws[k*72 + c] = decW[(size_t)c*576 + kc*DK + k];
        }
        __syncthreads();

        #pragma unroll 6
        for (int kq = 0; kq < DK/4; kq++) {
            float w[3][4];
            #pragma unroll
            for (int kk = 0; kk < 4; kk++)
                #pragma unroll
                for (int cc = 0; cc < 3; cc++)
                    w[cc][kk] = Ws[(kq*4+kk)*72 + colg*3 + cc];
            #pragma unroll
            for (int rr = 0; rr < 8; rr++) {
                float4 o = ((const float4*)Ot)[(rowg*8+rr)*(DK/4) + kq];
                #pragma unroll
                for (int cc = 0; cc < 3; cc++)
                    acc[rr][cc] = fmaf(o.x, w[cc][0],
                                  fmaf(o.y, w[cc][1],
                                  fmaf(o.z, w[cc][2],
                                  fmaf(o.w, w[cc][3], acc[rr][cc]))));
            }
        }
        __syncthreads();
    }

    #pragma unroll
    for (int rr = 0; rr < 8; rr++)
        #pragma unroll
        for (int cc = 0; cc < 3; cc++)
            out[(row0 + rowg*8 + rr)*72 + colg*3 + cc] =
                acc[rr][cc] + decB[colg*3 + cc];
}

extern "C" void kernel_launch(void* const* d_in, const int* in_sizes, int n_in,
                              void* d_out, int out_size)
{
    const float* src  = (const float*)d_in[0];
    const float* tgt  = (const float*)d_in[1];
    const float* encW = (const float*)d_in[2];
    const float* encB = (const float*)d_in[3];
    const float* xWl  = (const float*)d_in[4];
    const float* xWr  = (const float*)d_in[5];
    const float* xb   = (const float*)d_in[6];
    const float* hWl  = (const float*)d_in[7];
    const float* hWr  = (const float*)d_in[8];
    const float* hb   = (const float*)d_in[9];
    const float* gw   = (const float*)d_in[10];
    const float* gb   = (const float*)d_in[11];
    const float* decW = (const float*)d_in[12];
    const float* decB = (const float*)d_in[13];
    float* out = (float*)d_out;

    const int smem2 = (64*DK + 72*DK) * 4;
    cudaFuncSetAttribute(rec_kernel, cudaFuncAttributeMaxDynamicSharedMemorySize, SMEM1);
    cudaFuncSetAttribute(dec_kernel, cudaFuncAttributeMaxDynamicSharedMemorySize, smem2);

    rec_kernel<<<NBATCH, NT1, SMEM1>>>(src, tgt, encW, encB,
                                       xWl, xWr, xb, hWl, hWr, hb, gw, gb);
    dec_kernel<<<(NBATCH*TOUT)/64, NT2, smem2>>>(decW, decB, out);
}

// round 8
// speedup vs baseline: 4.0152x; 1.1693x over previous
#include <cuda_runtime.h>
#include <cuda_fp16.h>
#include <math.h>
#include <stdint.h>

#define NBATCH 1024
#define TSRC   32
#define TOUT   64
#define WARM   24
#define NT1    192
#define NT2    192

__device__ float g_O[(size_t)NBATCH * TOUT * 576];

__constant__ int c_nbr[24][5] = {
    {0,1,2,3,-1},{1,0,4,-1,-1},{2,0,5,-1,-1},{3,0,6,-1,-1},
    {4,1,7,-1,-1},{5,2,8,-1,-1},{6,3,9,-1,-1},{7,4,10,-1,-1},
    {8,5,11,-1,-1},{9,6,12,13,14},{10,7,-1,-1,-1},{11,8,-1,-1,-1},
    {12,9,15,-1,-1},{13,9,16,-1,-1},{14,9,17,-1,-1},{15,12,-1,-1,-1},
    {16,13,18,-1,-1},{17,14,19,-1,-1},{18,16,20,-1,-1},{19,17,21,-1,-1},
    {20,18,22,-1,-1},{21,19,23,-1,-1},{22,20,-1,-1,-1},{23,21,-1,-1,-1}};
__constant__ int c_cnt[24] = {4,3,3,3, 3,3,3,3, 3,5,2,2, 3,3,3,2, 3,3,3,3, 3,3,2,2};
__constant__ float c_inv[24] = {
    1.f/4,1.f/3,1.f/3,1.f/3, 1.f/3,1.f/3,1.f/3,1.f/3,
    1.f/3,1.f/5,1.f/2,1.f/2, 1.f/3,1.f/3,1.f/3,1.f/2,
    1.f/3,1.f/3,1.f/3,1.f/3, 1.f/3,1.f/3,1.f/2,1.f/2};

__device__ __forceinline__ float tanhap(float x) {
    float r; asm("tanh.approx.f32 %0, %1;" : "=f"(r) : "f"(x)); return r;
}
__device__ __forceinline__ float sigap(float x) {
    return fmaf(tanhap(0.5f * x), 0.5f, 0.5f);
}
__device__ __forceinline__ void mma16816(float* c, const uint32_t* a,
                                         uint32_t b0, uint32_t b1) {
    asm volatile("mma.sync.aligned.m16n8k16.row.col.f32.f16.f16.f32 "
        "{%0,%1,%2,%3}, {%4,%5,%6,%7}, {%8,%9}, {%0,%1,%2,%3};"
        : "+f"(c[0]), "+f"(c[1]), "+f"(c[2]), "+f"(c[3])
        : "r"(a[0]), "r"(a[1]), "r"(a[2]), "r"(a[3]), "r"(b0), "r"(b1));
}
__device__ __forceinline__ void ldsm4(uint32_t* r, uint32_t addr) {
    asm volatile("ldmatrix.sync.aligned.m8n8.x4.shared.b16 {%0,%1,%2,%3}, [%4];"
        : "=r"(r[0]), "=r"(r[1]), "=r"(r[2]), "=r"(r[3]) : "r"(addr));
}
__device__ __forceinline__ uint32_t s2u(const void* p) {
    return (uint32_t)__cvta_generic_to_shared(p);
}

// SMEM byte offsets. A/W rows padded to 104 halves (208B).
#define SA_HI 0                       // half [32][104]
#define SA_LO (SA_HI + 32*104*2)
#define SW_HI (SA_LO + 32*104*2)      // half [96][104]
#define SW_LO (SW_HI + 96*104*2)
#define SS    (SW_LO + 96*104*2)      // float [24][100]
#define SU    (SS + 24*100*4)         // float [24][48]: X 0-23, h 24-47
#define SBT   (SU + 24*48*4)          // float [96]
#define SGW   (SBT + 96*4)            // float [72]
#define SMEM1 (SGW + 72*4)

__global__ void __launch_bounds__(NT1, 3)
rec_kernel(const float* __restrict__ src, const float* __restrict__ tgt,
           const float* __restrict__ encW, const float* __restrict__ encB,
           const float* __restrict__ xWl, const float* __restrict__ xWr,
           const float* __restrict__ xb,
           const float* __restrict__ hWl, const float* __restrict__ hWr,
           const float* __restrict__ hb,
           const float* __restrict__ gw, const float* __restrict__ gb)
{
    extern __shared__ char smb[];
    __half* Ahi = (__half*)(smb + SA_HI);
    __half* Alo = (__half*)(smb + SA_LO);
    __half* Whi = (__half*)(smb + SW_HI);
    __half* Wlo = (__half*)(smb + SW_LO);
    float*  S   = (float*)(smb + SS);
    float*  U   = (float*)(smb + SU);
    float*  btot= (float*)(smb + SBT);
    float*  gwp = (float*)(smb + SGW);

    const int tid = threadIdx.x;
    const int n   = blockIdx.x;
    const int wid = tid >> 5, lane = tid & 31;
    const int g   = lane >> 2, t2 = (lane & 3) * 2;
    const int nb  = wid * 16;

    // ---- stage W split: row kc=k*4+g, col i in [aX|X|aH|h] order ----
    for (int e = tid; e < 96*96; e += NT1) {
        int kc = e / 96, i = e % 96;
        int k = kc >> 2, gg = kc & 3;
        float v;
        if      (i < 24) v = xWl[gg*576 + k*24 + i];
        else if (i < 48) v = xWr[gg*576 + k*24 + (i-24)];
        else if (i < 72) v = hWl[gg*576 + k*24 + (i-48)];
        else             v = hWr[gg*576 + k*24 + (i-72)];
        __half hh = __float2half_rn(v);
        Whi[kc*104 + i] = hh;
        Wlo[kc*104 + i] = __float2half_rn(v - __half2float(hh));
    }
    for (int e = tid; e < 96; e += NT1) {
        int k = e >> 2, gg = e & 3;
        btot[e] = xb[gg*24 + k] + hb[gg*24 + k] + gb[gg*24 + k];
    }
    for (int e = tid; e < 72; e += NT1) gwp[e] = gw[e];
    // zero all of A once (pad rows 24-31 stay zero forever)
    for (int e = tid; e < 32*52; e += NT1) {
        ((uint32_t*)Ahi)[e] = 0u;
        ((uint32_t*)Alo)[e] = 0u;
    }
    __syncthreads();   // A fully zeroed before partial overwrites below

    // init state: X = relu(enc(src[n, TSRC-WARM])), h = 0; X also into A
    #pragma unroll
    for (int r = 0; r < 3; r++) {
        int e = r*NT1 + tid; int j = e/24, h = e%24;
        const float* x = src + ((size_t)n*TSRC + (TSRC-WARM))*72 + j*3;
        float v = fmaxf(encB[h] + x[0]*encW[h*3] + x[1]*encW[h*3+1] + x[2]*encW[h*3+2], 0.f);
        U[j*48 + h]      = v;
        U[j*48 + 24 + h] = 0.f;
        __half vh = __float2half_rn(v);
        Ahi[j*104 + 24 + h] = vh;
        Alo[j*104 + 24 + h] = __float2half_rn(v - __half2float(vh));
    }
    __syncthreads();

    // per-lane ldmatrix base offsets (bytes)
    const int mi = lane >> 3;
    const int rA = (lane & 7) + ((mi & 1) << 3);
    const int cA = (mi >> 1) << 3;
    const uint32_t bAhi = s2u(Ahi), bAlo = s2u(Alo);
    const uint32_t bWhi = s2u(Whi), bWlo = s2u(Wlo);
    const uint32_t offA0 = (uint32_t)((rA       *104 + cA) * 2);
    const uint32_t offA1 = (uint32_t)(((16 + rA)*104 + cA) * 2);
    const uint32_t offW  = (uint32_t)(((nb + rA)*104 + cA) * 2);

    const int kth = tid % 24;
    const float gw0 = gwp[kth], gw1 = gwp[24+kth], gw2 = gwp[48+kth];
    const float4 bq = *(const float4*)&btot[kth*4];
    float c3[3] = {0.f, 0.f, 0.f};

    for (int t = 0; t < WARM + TOUT; t++) {
        // ---- (A) aggregation only: aX (A cols 0-23), aH (A cols 48-71) ----
        #pragma unroll
        for (int r = 0; r < 3; r++) {
            int e = r*NT1 + tid;          // 0..575
            int j = e / 24, q = e % 24;
            int typ = q / 12;             // 0: aX, 1: aH
            int kp = (q % 12) * 2;
            int so = typ ? 24 : 0;
            int dst = (typ ? 48 : 0) + kp;
            float x0 = 0.f, x1 = 0.f;
            int cnt = c_cnt[j];
            #pragma unroll
            for (int m = 0; m < 5; m++) if (m < cnt) {
                float2 u = *(const float2*)&U[c_nbr[j][m]*48 + so + kp];
                x0 += u.x; x1 += u.y;
            }
            x0 *= c_inv[j]; x1 *= c_inv[j];
            __half2 hi2 = __floats2half2_rn(x0, x1);
            float2 hf = __half22float2(hi2);
            *(__half2*)&Ahi[j*104 + dst] = hi2;
            *(__half2*)&Alo[j*104 + dst] = __floats2half2_rn(x0 - hf.x, x1 - hf.y);
        }
        __syncthreads();

        // ---- (C) tensor-core matvec via ldmatrix + m16n8k16 ----
        float cf[2][2][4];
        #pragma unroll
        for (int m = 0; m < 2; m++)
            #pragma unroll
            for (int nn = 0; nn < 2; nn++)
                #pragma unroll
                for (int q = 0; q < 4; q++) cf[m][nn][q] = 0.f;

        #pragma unroll
        for (int kt = 0; kt < 6; kt++) {
            uint32_t kb2 = (uint32_t)(kt * 32);   // 16 halves = 32 bytes
            uint32_t ah[2][4], al[2][4], wh[4], wl[4];
            ldsm4(ah[0], bAhi + offA0 + kb2);
            ldsm4(ah[1], bAhi + offA1 + kb2);
            ldsm4(al[0], bAlo + offA0 + kb2);
            ldsm4(al[1], bAlo + offA1 + kb2);
            ldsm4(wh,    bWhi + offW  + kb2);
            ldsm4(wl,    bWlo + offW  + kb2);
            #pragma unroll
            for (int m = 0; m < 2; m++)
                #pragma unroll
                for (int nn = 0; nn < 2; nn++) {
                    mma16816(cf[m][nn], ah[m], wh[nn], wh[nn+2]);
                    mma16816(cf[m][nn], ah[m], wl[nn], wl[nn+2]);
                    mma16816(cf[m][nn], al[m], wh[nn], wh[nn+2]);
                }
        }

        // ---- (D) C frags -> S[24][100] ----
        #pragma unroll
        for (int m = 0; m < 2; m++)
            #pragma unroll
            for (int nn = 0; nn < 2; nn++) {
                int col = nb + nn*8 + t2;
                int r0 = m*16 + g, r1 = r0 + 8;
                *(float2*)&S[r0*100 + col] = make_float2(cf[m][nn][0], cf[m][nn][1]);
                if (r1 < 24)
                    *(float2*)&S[r1*100 + col] = make_float2(cf[m][nn][2], cf[m][nn][3]);
            }
        __syncthreads();

        // ---- (E) gates; write U + A(X,h cols) + g_O ----
        float* dstg = g_O + ((size_t)n*TOUT + (t - WARM))*576;
        #pragma unroll
        for (int r = 0; r < 3; r++) {
            int j = r*8 + tid/24;
            float4 s4 = *(const float4*)&S[j*100 + kth*4];
            float c  = c3[r];
            float ig = sigap(fmaf(gw0, c, s4.x + bq.x));
            float fg = sigap(fmaf(gw1, c, s4.y + bq.y));
            float c2 = fmaf(fg, c, ig * tanhap(s4.z + bq.z));
            float og = sigap(fmaf(gw2, c2, s4.w + bq.w));
            float h2 = og * tanhap(c2);
            c3[r] = c2;
            U[j*48 + kth]      = og;
            U[j*48 + 24 + kth] = h2;
            __half oh = __float2half_rn(og);
            __half hh = __float2half_rn(h2);
            Ahi[j*104 + 24 + kth] = oh;
            Alo[j*104 + 24 + kth] = __float2half_rn(og - __half2float(oh));
            Ahi[j*104 + 72 + kth] = hh;
            Alo[j*104 + 72 + kth] = __float2half_rn(h2 - __half2float(hh));
            if (t >= WARM) dstg[r*192 + tid] = og;
        }
        __syncthreads();

        if (t == WARM - 1) {    // X <- relu(enc(tgt[n,0])); h/c carried
            #pragma unroll
            for (int r = 0; r < 3; r++) {
                int e = r*NT1 + tid; int j = e/24, h = e%24;
                const float* x = tgt + (size_t)n*(TOUT*72) + j*3;
                float v = fmaxf(encB[h] + x[0]*encW[h*3] + x[1]*encW[h*3+1] + x[2]*encW[h*3+2], 0.f);
                U[j*48 + h] = v;
                __half vh = __float2half_rn(v);
                Ahi[j*104 + 24 + h] = vh;
                Alo[j*104 + 24 + h] = __float2half_rn(v - __half2float(vh));
            }
            __syncthreads();
        }
    }
}

// ---------------- decoder GEMM: out[65536][72] = O[R][576] @ decW^T + b ----
#define DK 96
__global__ void __launch_bounds__(NT2)
dec_kernel(const float* __restrict__ decW, const float* __restrict__ decB,
           float* __restrict__ out)
{
    extern __shared__ float sm[];
    float* Ot = sm;               // [64][96]
    float* Ws = sm + 64*DK;       // [96][72], k-major

    const int tid  = threadIdx.x;
    const int rowg = tid / 24;
    const int colg = tid % 24;
    const size_t row0 = (size_t)blockIdx.x * 64;

    float acc[8][3];
    #pragma unroll
    for (int rr = 0; rr < 8; rr++)
        #pragma unroll
        for (int cc = 0; cc < 3; cc++) acc[rr][cc] = 0.f;

    for (int kc = 0; kc < 576/DK; kc++) {
        for (int e = tid; e < 64*DK/4; e += NT2) {
            int rr = e / (DK/4), kq = e % (DK/4);
            ((float4*)Ot)[rr*(DK/4) + kq] =
                ((const float4*)(g_O + (row0+rr)*576 + kc*DK))[kq];
        }
        for (int e = tid; e < 72*DK; e += NT2) {
            int c = e / DK, k = e % DK;
            Ws[k*72 + c] = decW[(size_t)c*576 + kc*DK + k];
        }
        __syncthreads();

        #pragma unroll 6
        for (int kq = 0; kq < DK/4; kq++) {
            float w[3][4];
            #pragma unroll
            for (int kk = 0; kk < 4; kk++)
                #pragma unroll
                for (int cc = 0; cc < 3; cc++)
                    w[cc][kk] = Ws[(kq*4+kk)*72 + colg*3 + cc];
            #pragma unroll
            for (int rr = 0; rr < 8; rr++) {
                float4 o = ((const float4*)Ot)[(rowg*8+rr)*(DK/4) + kq];
                #pragma unroll
                for (int cc = 0; cc < 3; cc++)
                    acc[rr][cc] = fmaf(o.x, w[cc][0],
                                  fmaf(o.y, w[cc][1],
                                  fmaf(o.z, w[cc][2],
                                  fmaf(o.w, w[cc][3], acc[rr][cc]))));
            }
        }
        __syncthreads();
    }

    #pragma unroll
    for (int rr = 0; rr < 8; rr++)
        #pragma unroll
        for (int cc = 0; cc < 3; cc++)
            out[(row0 + rowg*8 + rr)*72 + colg*3 + cc] =
                acc[rr][cc] + decB[colg*3 + cc];
}

extern "C" void kernel_launch(void* const* d_in, const int* in_sizes, int n_in,
                              void* d_out, int out_size)
{
    const float* src  = (const float*)d_in[0];
    const float* tgt  = (const float*)d_in[1];
    const float* encW = (const float*)d_in[2];
    const float* encB = (const float*)d_in[3];
    const float* xWl  = (const float*)d_in[4];
    const float* xWr  = (const float*)d_in[5];
    const float* xb   = (const float*)d_in[6];
    const float* hWl  = (const float*)d_in[7];
    const float* hWr  = (const float*)d_in[8];
    const float* hb   = (const float*)d_in[9];
    const float* gw   = (const float*)d_in[10];
    const float* gb   = (const float*)d_in[11];
    const float* decW = (const float*)d_in[12];
    const float* decB = (const float*)d_in[13];
    float* out = (float*)d_out;

    const int smem2 = (64*DK + 72*DK) * 4;
    cudaFuncSetAttribute(rec_kernel, cudaFuncAttributeMaxDynamicSharedMemorySize, SMEM1);
    cudaFuncSetAttribute(dec_kernel, cudaFuncAttributeMaxDynamicSharedMemorySize, smem2);

    rec_kernel<<<NBATCH, NT1, SMEM1>>>(src, tgt, encW, encB,
                                       xWl, xWr, xb, hWl, hWr, hb, gw, gb);
    dec_kernel<<<(NBATCH*TOUT)/64, NT2, smem2>>>(decW, decB, out);
}

// round 9
// speedup vs baseline: 4.2355x; 1.0549x over previous
#include <cuda_runtime.h>
#include <cuda_fp16.h>
#include <math.h>
#include <stdint.h>

#define NBATCH 1024
#define TSRC   32
#define TOUT   64
#define WARM   24
#define NT1    192
#define DNT    256

__device__ __half g_Ohi[(size_t)NBATCH * TOUT * 576];
__device__ __half g_Olo[(size_t)NBATCH * TOUT * 576];

__constant__ int c_nbr[24][5] = {
    {0,1,2,3,-1},{1,0,4,-1,-1},{2,0,5,-1,-1},{3,0,6,-1,-1},
    {4,1,7,-1,-1},{5,2,8,-1,-1},{6,3,9,-1,-1},{7,4,10,-1,-1},
    {8,5,11,-1,-1},{9,6,12,13,14},{10,7,-1,-1,-1},{11,8,-1,-1,-1},
    {12,9,15,-1,-1},{13,9,16,-1,-1},{14,9,17,-1,-1},{15,12,-1,-1,-1},
    {16,13,18,-1,-1},{17,14,19,-1,-1},{18,16,20,-1,-1},{19,17,21,-1,-1},
    {20,18,22,-1,-1},{21,19,23,-1,-1},{22,20,-1,-1,-1},{23,21,-1,-1,-1}};
__constant__ int c_cnt[24] = {4,3,3,3, 3,3,3,3, 3,5,2,2, 3,3,3,2, 3,3,3,3, 3,3,2,2};
__constant__ float c_inv[24] = {
    1.f/4,1.f/3,1.f/3,1.f/3, 1.f/3,1.f/3,1.f/3,1.f/3,
    1.f/3,1.f/5,1.f/2,1.f/2, 1.f/3,1.f/3,1.f/3,1.f/2,
    1.f/3,1.f/3,1.f/3,1.f/3, 1.f/3,1.f/3,1.f/2,1.f/2};

__device__ __forceinline__ float tanhap(float x) {
    float r; asm("tanh.approx.f32 %0, %1;" : "=f"(r) : "f"(x)); return r;
}
__device__ __forceinline__ float sigap(float x) {
    return fmaf(tanhap(0.5f * x), 0.5f, 0.5f);
}
__device__ __forceinline__ void mma16816(float* c, const uint32_t* a,
                                         uint32_t b0, uint32_t b1) {
    asm volatile("mma.sync.aligned.m16n8k16.row.col.f32.f16.f16.f32 "
        "{%0,%1,%2,%3}, {%4,%5,%6,%7}, {%8,%9}, {%0,%1,%2,%3};"
        : "+f"(c[0]), "+f"(c[1]), "+f"(c[2]), "+f"(c[3])
        : "r"(a[0]), "r"(a[1]), "r"(a[2]), "r"(a[3]), "r"(b0), "r"(b1));
}
__device__ __forceinline__ void ldsm4(uint32_t* r, uint32_t addr) {
    asm volatile("ldmatrix.sync.aligned.m8n8.x4.shared.b16 {%0,%1,%2,%3}, [%4];"
        : "=r"(r[0]), "=r"(r[1]), "=r"(r[2]), "=r"(r[3]) : "r"(addr));
}
__device__ __forceinline__ uint32_t s2u(const void* p) {
    return (uint32_t)__cvta_generic_to_shared(p);
}

// ---------------- rec kernel SMEM ----------------
#define SA_HI 0
#define SA_LO (SA_HI + 32*104*2)
#define SW_HI (SA_LO + 32*104*2)
#define SW_LO (SW_HI + 96*104*2)
#define SS    (SW_LO + 96*104*2)
#define SU    (SS + 24*100*4)
#define SBT   (SU + 24*48*4)
#define SGW   (SBT + 96*4)
#define SMEM1 (SGW + 72*4)

__global__ void __launch_bounds__(NT1, 3)
rec_kernel(const float* __restrict__ src, const float* __restrict__ tgt,
           const float* __restrict__ encW, const float* __restrict__ encB,
           const float* __restrict__ xWl, const float* __restrict__ xWr,
           const float* __restrict__ xb,
           const float* __restrict__ hWl, const float* __restrict__ hWr,
           const float* __restrict__ hb,
           const float* __restrict__ gw, const float* __restrict__ gb)
{
    extern __shared__ char smb[];
    __half* Ahi = (__half*)(smb + SA_HI);
    __half* Alo = (__half*)(smb + SA_LO);
    __half* Whi = (__half*)(smb + SW_HI);
    __half* Wlo = (__half*)(smb + SW_LO);
    float*  S   = (float*)(smb + SS);
    float*  U   = (float*)(smb + SU);
    float*  btot= (float*)(smb + SBT);
    float*  gwp = (float*)(smb + SGW);

    const int tid = threadIdx.x;
    const int n   = blockIdx.x;
    const int wid = tid >> 5, lane = tid & 31;
    const int g   = lane >> 2, t2 = (lane & 3) * 2;
    const int nb  = wid * 16;

    for (int e = tid; e < 96*96; e += NT1) {
        int kc = e / 96, i = e % 96;
        int k = kc >> 2, gg = kc & 3;
        float v;
        if      (i < 24) v = xWl[gg*576 + k*24 + i];
        else if (i < 48) v = xWr[gg*576 + k*24 + (i-24)];
        else if (i < 72) v = hWl[gg*576 + k*24 + (i-48)];
        else             v = hWr[gg*576 + k*24 + (i-72)];
        __half hh = __float2half_rn(v);
        Whi[kc*104 + i] = hh;
        Wlo[kc*104 + i] = __float2half_rn(v - __half2float(hh));
    }
    for (int e = tid; e < 96; e += NT1) {
        int k = e >> 2, gg = e & 3;
        btot[e] = xb[gg*24 + k] + hb[gg*24 + k] + gb[gg*24 + k];
    }
    for (int e = tid; e < 72; e += NT1) gwp[e] = gw[e];
    for (int e = tid; e < 32*52; e += NT1) {
        ((uint32_t*)Ahi)[e] = 0u;
        ((uint32_t*)Alo)[e] = 0u;
    }
    __syncthreads();

    #pragma unroll
    for (int r = 0; r < 3; r++) {
        int e = r*NT1 + tid; int j = e/24, h = e%24;
        const float* x = src + ((size_t)n*TSRC + (TSRC-WARM))*72 + j*3;
        float v = fmaxf(encB[h] + x[0]*encW[h*3] + x[1]*encW[h*3+1] + x[2]*encW[h*3+2], 0.f);
        U[j*48 + h]      = v;
        U[j*48 + 24 + h] = 0.f;
        __half vh = __float2half_rn(v);
        Ahi[j*104 + 24 + h] = vh;
        Alo[j*104 + 24 + h] = __float2half_rn(v - __half2float(vh));
    }
    __syncthreads();

    const int mi = lane >> 3;
    const int rA = (lane & 7) + ((mi & 1) << 3);
    const int cA = (mi >> 1) << 3;
    const uint32_t bAhi = s2u(Ahi), bAlo = s2u(Alo);
    const uint32_t bWhi = s2u(Whi), bWlo = s2u(Wlo);
    const uint32_t offA0 = (uint32_t)((rA       *104 + cA) * 2);
    const uint32_t offA1 = (uint32_t)(((16 + rA)*104 + cA) * 2);
    const uint32_t offW  = (uint32_t)(((nb + rA)*104 + cA) * 2);

    const int kth = tid % 24;
    const float gw0 = gwp[kth], gw1 = gwp[24+kth], gw2 = gwp[48+kth];
    const float4 bq = *(const float4*)&btot[kth*4];
    float c3[3] = {0.f, 0.f, 0.f};

    for (int t = 0; t < WARM + TOUT; t++) {
        #pragma unroll
        for (int r = 0; r < 3; r++) {
            int e = r*NT1 + tid;
            int j = e / 24, q = e % 24;
            int typ = q / 12;
            int kp = (q % 12) * 2;
            int so = typ ? 24 : 0;
            int dst = (typ ? 48 : 0) + kp;
            float x0 = 0.f, x1 = 0.f;
            int cnt = c_cnt[j];
            #pragma unroll
            for (int m = 0; m < 5; m++) if (m < cnt) {
                float2 u = *(const float2*)&U[c_nbr[j][m]*48 + so + kp];
                x0 += u.x; x1 += u.y;
            }
            x0 *= c_inv[j]; x1 *= c_inv[j];
            __half2 hi2 = __floats2half2_rn(x0, x1);
            float2 hf = __half22float2(hi2);
            *(__half2*)&Ahi[j*104 + dst] = hi2;
            *(__half2*)&Alo[j*104 + dst] = __floats2half2_rn(x0 - hf.x, x1 - hf.y);
        }
        __syncthreads();

        float cf[2][2][4];
        #pragma unroll
        for (int m = 0; m < 2; m++)
            #pragma unroll
            for (int nn = 0; nn < 2; nn++)
                #pragma unroll
                for (int q = 0; q < 4; q++) cf[m][nn][q] = 0.f;

        #pragma unroll
        for (int kt = 0; kt < 6; kt++) {
            uint32_t kb2 = (uint32_t)(kt * 32);
            uint32_t ah[2][4], al[2][4], wh[4], wl[4];
            ldsm4(ah[0], bAhi + offA0 + kb2);
            ldsm4(ah[1], bAhi + offA1 + kb2);
            ldsm4(al[0], bAlo + offA0 + kb2);
            ldsm4(al[1], bAlo + offA1 + kb2);
            ldsm4(wh,    bWhi + offW  + kb2);
            ldsm4(wl,    bWlo + offW  + kb2);
            #pragma unroll
            for (int m = 0; m < 2; m++)
                #pragma unroll
                for (int nn = 0; nn < 2; nn++) {
                    mma16816(cf[m][nn], ah[m], wh[nn], wh[nn+2]);
                    mma16816(cf[m][nn], ah[m], wl[nn], wl[nn+2]);
                    mma16816(cf[m][nn], al[m], wh[nn], wh[nn+2]);
                }
        }

        #pragma unroll
        for (int m = 0; m < 2; m++)
            #pragma unroll
            for (int nn = 0; nn < 2; nn++) {
                int col = nb + nn*8 + t2;
                int r0 = m*16 + g, r1 = r0 + 8;
                *(float2*)&S[r0*100 + col] = make_float2(cf[m][nn][0], cf[m][nn][1]);
                if (r1 < 24)
                    *(float2*)&S[r1*100 + col] = make_float2(cf[m][nn][2], cf[m][nn][3]);
            }
        __syncthreads();

        size_t obase = ((size_t)n*TOUT + (t - WARM))*576;
        #pragma unroll
        for (int r = 0; r < 3; r++) {
            int j = r*8 + tid/24;
            float4 s4 = *(const float4*)&S[j*100 + kth*4];
            float c  = c3[r];
            float ig = sigap(fmaf(gw0, c, s4.x + bq.x));
            float fg = sigap(fmaf(gw1, c, s4.y + bq.y));
            float c2 = fmaf(fg, c, ig * tanhap(s4.z + bq.z));
            float og = sigap(fmaf(gw2, c2, s4.w + bq.w));
            float h2 = og * tanhap(c2);
            c3[r] = c2;
            U[j*48 + kth]      = og;
            U[j*48 + 24 + kth] = h2;
            __half oh = __float2half_rn(og);
            __half ol = __float2half_rn(og - __half2float(oh));
            __half hh = __float2half_rn(h2);
            Ahi[j*104 + 24 + kth] = oh;
            Alo[j*104 + 24 + kth] = ol;
            Ahi[j*104 + 72 + kth] = hh;
            Alo[j*104 + 72 + kth] = __float2half_rn(h2 - __half2float(hh));
            if (t >= WARM) {
                g_Ohi[obase + r*192 + tid] = oh;
                g_Olo[obase + r*192 + tid] = ol;
            }
        }
        __syncthreads();

        if (t == WARM - 1) {
            #pragma unroll
            for (int r = 0; r < 3; r++) {
                int e = r*NT1 + tid; int j = e/24, h = e%24;
                const float* x = tgt + (size_t)n*(TOUT*72) + j*3;
                float v = fmaxf(encB[h] + x[0]*encW[h*3] + x[1]*encW[h*3+1] + x[2]*encW[h*3+2], 0.f);
                U[j*48 + h] = v;
                __half vh = __float2half_rn(v);
                Ahi[j*104 + 24 + h] = vh;
                Alo[j*104 + 24 + h] = __float2half_rn(v - __half2float(vh));
            }
            __syncthreads();
        }
    }
}

// ---------------- decoder: tensor-core GEMM [65536x576]@[576x72] ----------------
// 512 CTAs x 256 thr; warp owns 16-row M-tile x all 72 N-cols; K chunk 96.
#define DA_HI 0
#define DA_LO (DA_HI + 128*104*2)
#define DW_HI (DA_LO + 128*104*2)
#define DW_LO (DW_HI + 96*104*2)
#define SMEM2 (DW_LO + 96*104*2)

__global__ void __launch_bounds__(DNT, 2)
dec_kernel(const float* __restrict__ decW, const float* __restrict__ decB,
           float* __restrict__ out)
{
    extern __shared__ char smb[];
    __half* Ahi = (__half*)(smb + DA_HI);   // [128][104]
    __half* Alo = (__half*)(smb + DA_LO);
    __half* Whi = (__half*)(smb + DW_HI);   // [96][104], row = out col (pad >71 = 0)
    __half* Wlo = (__half*)(smb + DW_LO);

    const int tid = threadIdx.x;
    const int wid = tid >> 5, lane = tid & 31;
    const int g = lane >> 2, t2 = (lane & 3) * 2;
    const size_t row0 = (size_t)blockIdx.x * 128;

    const int mi = lane >> 3;
    const int rA = (lane & 7) + ((mi & 1) << 3);
    const int cA = (mi >> 1) << 3;
    const uint32_t bAhi = s2u(Ahi), bAlo = s2u(Alo);
    const uint32_t bWhi = s2u(Whi), bWlo = s2u(Wlo);
    const uint32_t offA = (uint32_t)(((wid*16 + rA)*104 + cA) * 2);
    const uint32_t offW = (uint32_t)((rA*104 + cA) * 2);

    float acc[9][4];
    #pragma unroll
    for (int nt = 0; nt < 9; nt++)
        #pragma unroll
        for (int q = 0; q < 4; q++) acc[nt][q] = 0.f;

    for (int kc = 0; kc < 6; kc++) {
        // stage A: 128 rows x 96 halves per plane (u32 loads, coalesced per row)
        for (int e = tid; e < 128*48; e += DNT) {
            int r = e / 48, kq = e % 48;
            size_t go = (row0 + r)*576 + kc*96 + kq*2;
            *(uint32_t*)&Ahi[r*104 + kq*2] = *(const uint32_t*)&g_Ohi[go];
            *(uint32_t*)&Alo[r*104 + kq*2] = *(const uint32_t*)&g_Olo[go];
        }
        // stage W chunk with fp16 split (rows 72..95 zero)
        for (int e = tid; e < 96*96; e += DNT) {
            int c = e / 96, k = e % 96;
            float v = (c < 72) ? decW[(size_t)c*576 + kc*96 + k] : 0.f;
            __half hh = __float2half_rn(v);
            Whi[c*104 + k] = hh;
            Wlo[c*104 + k] = __float2half_rn(v - __half2float(hh));
        }
        __syncthreads();

        #pragma unroll
        for (int kt = 0; kt < 6; kt++) {
            uint32_t kb2 = (uint32_t)(kt * 32);
            uint32_t ah[4], al[4], wh[5][4], wl[5][4];
            ldsm4(ah, bAhi + offA + kb2);
            ldsm4(al, bAlo + offA + kb2);
            #pragma unroll
            for (int q = 0; q < 5; q++) {
                ldsm4(wh[q], bWhi + offW + (uint32_t)(q*16*104*2) + kb2);
                ldsm4(wl[q], bWlo + offW + (uint32_t)(q*16*104*2) + kb2);
            }
            #pragma unroll
            for (int nt = 0; nt < 9; nt++) {
                uint32_t b0h = wh[nt>>1][nt&1], b1h = wh[nt>>1][(nt&1)+2];
                uint32_t b0l = wl[nt>>1][nt&1], b1l = wl[nt>>1][(nt&1)+2];
                mma16816(acc[nt], ah, b0h, b1h);
                mma16816(acc[nt], ah, b0l, b1l);
                mma16816(acc[nt], al, b0h, b1h);
            }
        }
        __syncthreads();
    }

    #pragma unroll
    for (int nt = 0; nt < 9; nt++) {
        int col = nt*8 + t2;
        float b0 = decB[col], b1 = decB[col+1];
        size_t r0 = row0 + wid*16 + g;
        *(float2*)&out[r0*72 + col]     = make_float2(acc[nt][0]+b0, acc[nt][1]+b1);
        *(float2*)&out[(r0+8)*72 + col] = make_float2(acc[nt][2]+b0, acc[nt][3]+b1);
    }
}

extern "C" void kernel_launch(void* const* d_in, const int* in_sizes, int n_in,
                              void* d_out, int out_size)
{
    const float* src  = (const float*)d_in[0];
    const float* tgt  = (const float*)d_in[1];
    const float* encW = (const float*)d_in[2];
    const float* encB = (const float*)d_in[3];
    const float* xWl  = (const float*)d_in[4];
    const float* xWr  = (const float*)d_in[5];
    const float* xb   = (const float*)d_in[6];
    const float* hWl  = (const float*)d_in[7];
    const float* hWr  = (const float*)d_in[8];
    const float* hb   = (const float*)d_in[9];
    const float* gw   = (const float*)d_in[10];
    const float* gb   = (const float*)d_in[11];
    const float* decW = (const float*)d_in[12];
    const float* decB = (const float*)d_in[13];
    float* out = (float*)d_out;

    cudaFuncSetAttribute(rec_kernel, cudaFuncAttributeMaxDynamicSharedMemorySize, SMEM1);
    cudaFuncSetAttribute(dec_kernel, cudaFuncAttributeMaxDynamicSharedMemorySize, SMEM2);

    rec_kernel<<<NBATCH, NT1, SMEM1>>>(src, tgt, encW, encB,
                                       xWl, xWr, xb, hWl, hWr, hb, gw, gb);
    dec_kernel<<<(NBATCH*TOUT)/128, DNT, SMEM2>>>(decW, decB, out);
}